// round 17
// baseline (speedup 1.0000x reference)
#include <cuda_runtime.h>
#include <cuda_fp16.h>

#define TT   1000
#define NCH  4096

// scratch (no cudaMalloc allowed)
__device__ float g_seq[NCH * TT];     // LSTM input, [chain][t], 16 MB
__device__ float g_feat[NCH * 32];    // [chain][ h_fwd(16) | h_bwd(16) ]

__device__ __forceinline__ float tanhfast(float x) {
    float r; asm("tanh.approx.f32 %0, %1;" : "=f"(r) : "f"(x)); return r;
}
__device__ __forceinline__ unsigned h2tanh(unsigned x) {
    unsigned r; asm("tanh.approx.f16x2 %0, %1;" : "=r"(r) : "r"(x)); return r;
}
__device__ __forceinline__ unsigned f2h2(float a, float b) {
    __half2 v = __floats2half2_rn(a, b);   // a -> low half
    return *(unsigned*)&v;
}

// ---------------------------------------------------------------------------
// Packed 2-state LSTM activation: 5 MUFU.f16x2 per PAIR of states.
// Gates i,f,o pre-halved (sigmoid(x)=0.5*tanh(x/2)+0.5); c kept in fp32.
// Returns packed f16x2 h (lo=state0, hi=state1) ready for publish;
// also exports the packed so for the final fp32 h reconstruction.
// ---------------------------------------------------------------------------
__device__ __forceinline__ unsigned lstm_act_pair(
    float gi0, float gi1, float gf0, float gf1,
    float gg0, float gg1, float go0, float go1,
    float& c0, float& c1, unsigned& so_out)
{
    const __half2 H05 = __floats2half2_rn(0.5f, 0.5f);
    unsigned ti = h2tanh(f2h2(gi0, gi1));           // MUFU f16x2
    unsigned tf = h2tanh(f2h2(gf0, gf1));           // MUFU f16x2
    unsigned tg = h2tanh(f2h2(gg0, gg1));           // MUFU f16x2
    unsigned to = h2tanh(f2h2(go0, go1));           // MUFU f16x2
    const __half2 si = __hfma2(*(__half2*)&ti, H05, H05);
    const __half2 sf = __hfma2(*(__half2*)&tf, H05, H05);
    const __half2 so = __hfma2(*(__half2*)&to, H05, H05);
    const __half2 pr = __hmul2(si, *(__half2*)&tg); // si * tanh(g)
    c0 = fmaf(__half2float(__low2half(sf)),  c0, __half2float(__low2half(pr)));
    c1 = fmaf(__half2float(__high2half(sf)), c1, __half2float(__high2half(pr)));
    unsigned tc = h2tanh(f2h2(c0, c1));             // MUFU f16x2
    const __half2 h2v = __hmul2(so, *(__half2*)&tc);
    so_out = *(unsigned*)&so;
    return *(unsigned*)&h2v;
}

__device__ __forceinline__ unsigned pack_h2(float a, float b) {
    __half2 v = __halves2half2(__float2half_rn(a), __float2half_rn(b));
    return *(unsigned*)&v;
}

__device__ __forceinline__ void mma16816(float d[4], const unsigned a[4], const unsigned b[2]) {
    asm volatile("mma.sync.aligned.m16n8k16.row.col.f32.f16.f16.f32 "
                 "{%0,%1,%2,%3}, {%4,%5,%6,%7}, {%8,%9}, {%0,%1,%2,%3};"
                 : "+f"(d[0]), "+f"(d[1]), "+f"(d[2]), "+f"(d[3])
                 : "r"(a[0]), "r"(a[1]), "r"(a[2]), "r"(a[3]),
                   "r"(b[0]), "r"(b[1]));
}

__device__ __forceinline__ float gelu_exact(float v) {
    return 0.5f * v * (1.0f + erff(v * 0.70710678118654752f));
}

// ---------------------------------------------------------------------------
// Kernel 1: fused depthwise-conv(5,pad2)+BN+GELU x2. One block per (b,c) row.
// ---------------------------------------------------------------------------
__global__ void __launch_bounds__(256) prep_kernel(
    const float* __restrict__ x,
    const float* __restrict__ c1w, const float* __restrict__ c1b,
    const float* __restrict__ b1g, const float* __restrict__ b1b,
    const float* __restrict__ b1m, const float* __restrict__ b1v,
    const float* __restrict__ c2w, const float* __restrict__ c2b,
    const float* __restrict__ b2g, const float* __restrict__ b2b,
    const float* __restrict__ b2m, const float* __restrict__ b2v)
{
    __shared__ float xs[TT + 4];
    __shared__ float ys[TT + 4];

    const int chain = blockIdx.x;
    const int ch    = chain & 63;
    const int tid   = threadIdx.x;

    if (tid < 2) {
        xs[tid] = 0.0f; xs[TT + 2 + tid] = 0.0f;
        ys[tid] = 0.0f; ys[TT + 2 + tid] = 0.0f;
    }
    const float* xr = x + (size_t)chain * TT;
    for (int t = tid; t < TT; t += 256) xs[t + 2] = xr[t];

    const float w0 = c1w[ch * 5 + 0], w1 = c1w[ch * 5 + 1], w2 = c1w[ch * 5 + 2],
                w3 = c1w[ch * 5 + 3], w4 = c1w[ch * 5 + 4];
    const float s1 = b1g[ch] * rsqrtf(b1v[ch] + 1e-5f);
    const float d1 = (c1b[ch] - b1m[ch]) * s1 + b1b[ch];

    __syncthreads();
    for (int t = tid; t < TT; t += 256) {
        float a = xs[t] * w0;
        a = fmaf(xs[t + 1], w1, a);
        a = fmaf(xs[t + 2], w2, a);
        a = fmaf(xs[t + 3], w3, a);
        a = fmaf(xs[t + 4], w4, a);
        ys[t + 2] = gelu_exact(fmaf(a, s1, d1));
    }

    const float u0 = c2w[ch * 5 + 0], u1 = c2w[ch * 5 + 1], u2 = c2w[ch * 5 + 2],
                u3 = c2w[ch * 5 + 3], u4 = c2w[ch * 5 + 4];
    const float s2 = b2g[ch] * rsqrtf(b2v[ch] + 1e-5f);
    const float d2 = (c2b[ch] - b2m[ch]) * s2 + b2b[ch];

    __syncthreads();
    float* outr = g_seq + (size_t)chain * TT;
    for (int t = tid; t < TT; t += 256) {
        float a = ys[t] * u0;
        a = fmaf(ys[t + 1], u1, a);
        a = fmaf(ys[t + 2], u2, a);
        a = fmaf(ys[t + 3], u3, a);
        a = fmaf(ys[t + 4], u4, a);
        outr[t] = gelu_exact(fmaf(a, s2, d2));
    }
}

// ---------------------------------------------------------------------------
// Kernel 2: LSTM via HMMA, 8 same-direction chains per warp (full N=8).
// R16 = R15 structure (plain-f16 h, 4 HMMA/step, smem h-exchange, one
// syncwarp/step) + PACKED f16x2 activation: 5 MUFU per state-PAIR
// (tanh.approx.f16x2), c kept fp32. Packed h is published directly.
// Final h reconstructed in fp32 from fp32 c + last so.
// Gates i,f,o pre-halved at fragment load (sigmoid-from-tanh).
// ---------------------------------------------------------------------------
__global__ void __launch_bounds__(128) lstm_kernel(
    const float* __restrict__ wihf, const float* __restrict__ whhf,
    const float* __restrict__ bihf, const float* __restrict__ bhhf,
    const float* __restrict__ wihr, const float* __restrict__ whhr,
    const float* __restrict__ bihr, const float* __restrict__ bhhr)
{
    // per-warp h buffer, f16x2 (chains 2p|2p+1): [2 parity][4 pairs][16 units]
    __shared__ __align__(16) unsigned hbuf_s[4][2][4][16];

    const int tid  = threadIdx.x;
    const int wid  = tid >> 5;
    const int lane = tid & 31;
    const int wg   = blockIdx.x * 4 + wid;          // 0..1023
    const bool bwd = (wg >= 512);
    const int cb   = 8 * (bwd ? wg - 512 : wg);     // chain base (8 chains)

    const float* wih = bwd ? wihr : wihf;
    const float* whh = bwd ? whhr : whhf;
    const float* bih = bwd ? bihr : bihf;
    const float* bhh = bwd ? bhhr : bhhf;

    unsigned* hbW = &hbuf_s[wid][0][0][0];
    for (int i = lane; i < 2 * 4 * 16; i += 32) hbW[i] = 0u;

    const int g = lane >> 2;      // MMA group: D rows g, g+8; B col(chain) g
    const int t = lane & 3;       // MMA thread-in-group: D cols 2t, 2t+1

    // ---- A fragments (f16 W_hh), bias and w_ih per gate tile ----
    // Gates i (m=0), f (m=1), o (m=3): scaled by 0.5 (sigmoid-from-tanh).
    unsigned Ahi[4][4];
    float bb0[4], bb1[4], wi0[4], wi1[4];
#pragma unroll
    for (int m = 0; m < 4; m++) {
        const float sc = (m == 2) ? 1.0f : 0.5f;
        const int r0 = m * 16 + g;
        const int r1 = r0 + 8;
        const float* W0 = whh + r0 * 16;
        const float* W1 = whh + r1 * 16;
        Ahi[m][0] = pack_h2(sc * W0[2*t],   sc * W0[2*t+1]);
        Ahi[m][1] = pack_h2(sc * W1[2*t],   sc * W1[2*t+1]);
        Ahi[m][2] = pack_h2(sc * W0[2*t+8], sc * W0[2*t+9]);
        Ahi[m][3] = pack_h2(sc * W1[2*t+8], sc * W1[2*t+9]);
        bb0[m] = sc * (bih[r0] + bhh[r0]);
        bb1[m] = sc * (bih[r1] + bhh[r1]);
        wi0[m] = sc * wih[r0];
        wi1[m] = sc * wih[r1];
    }

    // x staging: lane = 4*chain + substep; coalesced 16B runs per chain
    const int xc  = lane >> 2;          // chain 0..7
    const int xs_ = lane & 3;           // substep 0..3
    const float* seqc = g_seq + (size_t)(cb + xc) * TT;

    // B-build addressing: need chain g -> pair g>>1, slot g&1
    const int bpair = g >> 1;
    const unsigned psel = (g & 1) ? 0x7632u : 0x5410u;

    // states owned by this lane: q=0 ->(g,2t)  q=1 ->(g,2t+1)
    //                            q=2 ->(g+8,2t) q=3 ->(g+8,2t+1)
    float c4[4] = {0.0f, 0.0f, 0.0f, 0.0f};
    unsigned so01 = 0u, so23 = 0u;     // last-step packed sigmoid(o)

    int par = 0;
    for (int r = 0; r < 250; r++) {
        const int tt = r * 4 + xs_;
        const float xv = seqc[bwd ? (TT - 1 - tt) : tt];

#pragma unroll
        for (int s = 0; s < 4; s++) {
            __syncwarp();      // prev step's h writes -> visible for B-build

            // broadcast x of chains 2t, 2t+1 for this step
            const float xA = __shfl_sync(0xffffffffu, xv, 8 * t + s);
            const float xB = __shfl_sync(0xffffffffu, xv, 8 * t + 4 + s);

            // B fragment: h(t-1) units {2t,2t+1} and {2t+8,2t+9}, chain g
            const unsigned* hbp = hbW + par * 64 + bpair * 16;
            const uint2 u01 = *(const uint2*)(hbp + 2 * t);       // units 2t,2t+1
            const uint2 u89 = *(const uint2*)(hbp + 2 * t + 8);   // units 2t+8,2t+9
            unsigned B[2];
            B[0] = __byte_perm(u01.x, u01.y, psel);
            B[1] = __byte_perm(u89.x, u89.y, psel);

            // D init: bias + w_ih * x  (rows g, g+8; cols 2t, 2t+1)
            float d[4][4];
#pragma unroll
            for (int m = 0; m < 4; m++) {
                d[m][0] = fmaf(wi0[m], xA, bb0[m]);
                d[m][1] = fmaf(wi0[m], xB, bb0[m]);
                d[m][2] = fmaf(wi1[m], xA, bb1[m]);
                d[m][3] = fmaf(wi1[m], xB, bb1[m]);
            }

            // 4 HMMA: W_f16 * h_f16 (fp32 accumulate)
#pragma unroll
            for (int m = 0; m < 4; m++)
                mma16816(d[m], Ahi[m], B);

            // packed activation: pair (q0,q1) and pair (q2,q3)
            const unsigned hp01 = lstm_act_pair(
                d[0][0], d[0][1], d[1][0], d[1][1],
                d[2][0], d[2][1], d[3][0], d[3][1],
                c4[0], c4[1], so01);
            const unsigned hp23 = lstm_act_pair(
                d[0][2], d[0][3], d[1][2], d[1][3],
                d[2][2], d[2][3], d[3][2], d[3][3],
                c4[2], c4[3], so23);

            // publish packed h directly
            unsigned* ho = hbW + (par ^ 1) * 64 + t * 16;
            ho[g]     = hp01;
            ho[g + 8] = hp23;

            par ^= 1;
        }
    }

    // final h in fp32: h = so_last * tanh(c_fp32)
    float hout[4];
    hout[0] = __half2float(__low2half(*(__half2*)&so01))  * tanhfast(c4[0]);
    hout[1] = __half2float(__high2half(*(__half2*)&so01)) * tanhfast(c4[1]);
    hout[2] = __half2float(__low2half(*(__half2*)&so23))  * tanhfast(c4[2]);
    hout[3] = __half2float(__high2half(*(__half2*)&so23)) * tanhfast(c4[3]);

    // final h: lane owns (unit g, chains cb+2t, cb+2t+1) and (unit g+8, same)
    const int off = bwd ? 16 : 0;
    g_feat[(cb + 2 * t)     * 32 + off + g]     = hout[0];
    g_feat[(cb + 2 * t + 1) * 32 + off + g]     = hout[1];
    g_feat[(cb + 2 * t)     * 32 + off + g + 8] = hout[2];
    g_feat[(cb + 2 * t + 1) * 32 + off + g + 8] = hout[3];
}

// ---------------------------------------------------------------------------
// Kernel 3: out[n,e] = feat[n,:] . lin_w[e,:] + lin_b[e]
// ---------------------------------------------------------------------------
__global__ void __launch_bounds__(256) linear_kernel(
    const float* __restrict__ lw, const float* __restrict__ lb,
    float* __restrict__ out)
{
    const int idx = blockIdx.x * 256 + threadIdx.x;    // 131072 total
    const int n = idx >> 5;
    const int e = idx & 31;
    const float* f = g_feat + n * 32;
    const float* wp = lw + e * 32;
    float acc = lb[e];
#pragma unroll
    for (int k = 0; k < 32; k++) acc = fmaf(f[k], wp[k], acc);
    out[idx] = acc;
}

// ---------------------------------------------------------------------------
extern "C" void kernel_launch(void* const* d_in, const int* in_sizes, int n_in,
                              void* d_out, int out_size)
{
    const float* x      = (const float*)d_in[0];
    const float* c1w    = (const float*)d_in[1];
    const float* c1b    = (const float*)d_in[2];
    const float* b1g    = (const float*)d_in[3];
    const float* b1b    = (const float*)d_in[4];
    const float* b1m    = (const float*)d_in[5];
    const float* b1v    = (const float*)d_in[6];
    const float* c2w    = (const float*)d_in[7];
    const float* c2b    = (const float*)d_in[8];
    const float* b2g    = (const float*)d_in[9];
    const float* b2b    = (const float*)d_in[10];
    const float* b2m    = (const float*)d_in[11];
    const float* b2v    = (const float*)d_in[12];
    const float* wihf   = (const float*)d_in[13];
    const float* whhf   = (const float*)d_in[14];
    const float* bihf   = (const float*)d_in[15];
    const float* bhhf   = (const float*)d_in[16];
    const float* wihr   = (const float*)d_in[17];
    const float* whhr   = (const float*)d_in[18];
    const float* bihr   = (const float*)d_in[19];
    const float* bhhr   = (const float*)d_in[20];
    const float* lw     = (const float*)d_in[21];
    const float* lb     = (const float*)d_in[22];
    float* out = (float*)d_out;

    prep_kernel<<<NCH, 256>>>(x, c1w, c1b, b1g, b1b, b1m, b1v,
                              c2w, c2b, b2g, b2b, b2m, b2v);
    lstm_kernel<<<256, 128>>>(wihf, whhf, bihf, bhhf,
                              wihr, whhr, bihr, bhhr);
    linear_kernel<<<(NCH * 32) / 256, 256>>>(lw, lb, out);
}